// round 7
// baseline (speedup 1.0000x reference)
#include <cuda_runtime.h>
#include <cuda_fp16.h>
#include <cstdint>

// Problem constants
constexpr int Bb = 108;
constexpr int Nn = 392;
constexpr int Hh = 4;
constexpr int HO = 256;
constexpr int BN = Bb * Nn;     // 42336
constexpr int BH = Bb * Hh;     // 432

#define ALPHA_C   0.2f
#define LEAKY_C   0.2f

// Scratch (allocation-free: __device__ globals)
__device__ __half g_xH[(size_t)BN * HO];
__device__ __half g_wTh[256 * 256];
__device__ __half g_kTh[256 * 256];
__device__ __half g_aH[Nn * Nn];
__device__ __half g_mlpH[(size_t)BN * HO];
__device__ __half g_mlpTh[(size_t)BN * HO];
__device__ __half g_zH[(size_t)BN * HO];
__device__ __half g_xpH[(size_t)BN * HO];
__device__ __half g_xpHT[(size_t)BH * 64 * Nn];
__device__ float  g_kak[256 * 8];            // [i][h*2+{0:self,1:neigh}]
__device__ float  g_sT[BH * Nn];
__device__ float  g_ngT[BH * Nn];
__device__ unsigned g_mbits[Nn * 13];

// ---------------------------------------------------------------------------
// PTX helpers
// ---------------------------------------------------------------------------
__device__ __forceinline__ void mma_f16(float* c, const uint32_t* a,
                                        uint32_t b0, uint32_t b1) {
    asm volatile(
        "mma.sync.aligned.m16n8k16.row.col.f32.f16.f16.f32 "
        "{%0,%1,%2,%3}, {%4,%5,%6,%7}, {%8,%9}, {%0,%1,%2,%3};"
        : "+f"(c[0]), "+f"(c[1]), "+f"(c[2]), "+f"(c[3])
        : "r"(a[0]), "r"(a[1]), "r"(a[2]), "r"(a[3]), "r"(b0), "r"(b1));
}
__device__ __forceinline__ void cp16(uint32_t dst, const void* src, int sz) {
    asm volatile("cp.async.cg.shared.global [%0], [%1], 16, %2;"
                 :: "r"(dst), "l"(src), "r"(sz));
}
#define CP_COMMIT() asm volatile("cp.async.commit_group;")
#define CP_WAIT(N)  asm volatile("cp.async.wait_group %0;" :: "n"(N))

constexpr int STU = 20;          // u32 per smem row (40 halves) -> conflict-free

// ---------------------------------------------------------------------------
// fp16 GEMM: C[M,256] = A[M,K] @ B^T (B [256,K] k-major). All outputs fp16.
// EPI 0: sigmoid(acc+bias[col]) | 1: plain | 2: APPNP blend with extraH
// 256 thr, CTA 128x128, warp 64x32, ktile 32, 3-stage cp.async.
// ---------------------------------------------------------------------------
template <int EPI>
__global__ void __launch_bounds__(256, 2)
tc_gemm(const __half* __restrict__ A, long strideA,
        const __half* __restrict__ Bm, long strideB,
        const void* __restrict__ extra, long strideE,
        __half* __restrict__ C, long strideC,
        int M, int K, int S)
{
    extern __shared__ char smraw[];
    const int t = threadIdx.x;
    const int m0 = blockIdx.x * 128;
    const int col0 = blockIdx.y * 128;
    A += (size_t)blockIdx.z * strideA;
    Bm += (size_t)blockIdx.z * strideB;
    C += (size_t)blockIdx.z * strideC;

    const int w = t >> 5, lane = t & 31;
    const int g = lane >> 2, tg = lane & 3;
    const int warpM = (w & 1) * 64;
    const int warpN = (w >> 1) * 32;

    constexpr int STAGE_B = 2 * 128 * STU * 4;
    const uint32_t smb = (uint32_t)__cvta_generic_to_shared(smraw);

    float acc[4][4][4];
    #pragma unroll
    for (int i = 0; i < 4; i++)
        #pragma unroll
        for (int j = 0; j < 4; j++)
            #pragma unroll
            for (int q = 0; q < 4; q++) acc[i][j][q] = 0.0f;

    auto stage = [&](int s, int p) {
        const int k0 = s * 32;
        const uint32_t As = smb + p * STAGE_B;
        const uint32_t Bs = As + 128 * STU * 4;
        #pragma unroll
        for (int i = 0; i < 2; i++) {
            int idx = t + i * 256;
            int row = idx >> 2, q = idx & 3;
            int gr = m0 + row, k = k0 + q * 8;
            int sz = (gr < M && k + 8 <= K) ? 16 : 0;
            const void* src = sz ? (const void*)(A + (size_t)gr * K + k) : (const void*)A;
            cp16(As + (row * STU + q * 4) * 4, src, sz);
        }
        #pragma unroll
        for (int i = 0; i < 2; i++) {
            int idx = t + i * 256;
            int row = idx >> 2, q = idx & 3;
            int k = k0 + q * 8;
            int sz = (k + 8 <= K) ? 16 : 0;
            const void* src = sz ? (const void*)(Bm + (size_t)(col0 + row) * K + k)
                                 : (const void*)Bm;
            cp16(Bs + (row * STU + q * 4) * 4, src, sz);
        }
        CP_COMMIT();
    };

    auto compute = [&](int p) {
        const uint32_t* As = (const uint32_t*)(smraw + p * STAGE_B);
        const uint32_t* Bs = As + 128 * STU;
        #pragma unroll
        for (int ks = 0; ks < 2; ks++) {
            const int kb = ks * 8;
            uint32_t af[4][4];
            #pragma unroll
            for (int mt = 0; mt < 4; mt++) {
                const int r = warpM + mt * 16;
                af[mt][0] = As[(r + g) * STU + kb + tg];
                af[mt][1] = As[(r + g + 8) * STU + kb + tg];
                af[mt][2] = As[(r + g) * STU + kb + tg + 4];
                af[mt][3] = As[(r + g + 8) * STU + kb + tg + 4];
            }
            #pragma unroll
            for (int nt = 0; nt < 4; nt++) {
                const int c = warpN + nt * 8 + g;
                uint32_t b0 = Bs[c * STU + kb + tg];
                uint32_t b1 = Bs[c * STU + kb + tg + 4];
                #pragma unroll
                for (int mt = 0; mt < 4; mt++)
                    mma_f16(acc[mt][nt], af[mt], b0, b1);
            }
        }
    };

    stage(0, 0);
    if (S > 1) stage(1, 1);
    for (int s = 0; s < S; s++) {
        const int p = s % 3;
        if (s + 2 < S) { stage(s + 2, (s + 2) % 3); CP_WAIT(2); }
        else if (s + 1 < S) { CP_WAIT(1); }
        else { CP_WAIT(0); }
        __syncthreads();
        compute(p);
        __syncthreads();
    }

    #pragma unroll
    for (int mt = 0; mt < 4; mt++) {
        #pragma unroll
        for (int half = 0; half < 2; half++) {
            int r = m0 + warpM + mt * 16 + g + half * 8;
            if (r >= M) continue;
            #pragma unroll
            for (int nt = 0; nt < 4; nt++) {
                int cc = col0 + warpN + nt * 8 + tg * 2;
                float v0 = acc[mt][nt][half * 2 + 0];
                float v1 = acc[mt][nt][half * 2 + 1];
                float o0, o1;
                if (EPI == 0) {
                    float2 bb = *(const float2*)((const float*)extra + cc);
                    o0 = 1.0f / (1.0f + __expf(-(v0 + bb.x)));
                    o1 = 1.0f / (1.0f + __expf(-(v1 + bb.y)));
                } else if (EPI == 2) {
                    const __half* eH = (const __half*)extra + (size_t)blockIdx.z * strideE;
                    __half2 e2 = *(const __half2*)(eH + (size_t)r * 256 + cc);
                    float2 e = __half22float2(e2);
                    o0 = (1.0f - ALPHA_C) * v0 + ALPHA_C * e.x;
                    o1 = (1.0f - ALPHA_C) * v1 + ALPHA_C * e.y;
                } else {
                    o0 = v0; o1 = v1;
                }
                *(__half2*)(C + (size_t)r * 256 + cc) = __floats2half2_rn(o0, o1);
            }
        }
    }
}
constexpr unsigned SMEM_TC = 3u * 2u * 128u * STU * 4u;    // 61440 B

// ---------------------------------------------------------------------------
// Fused AV: out[n, h*64+o] = (sum_m e(n,m) * xp[m,h,o]) / (sum_m e(n,m)) +bias, ELU
// e(n,m) = exp(leaky(s[n]+ng[m])), masked -> 0.  A-fragments computed inline,
// rowsum accumulated in registers. CTA 128 rows (8 warps x 16) x 64 cols.
// B (xpHT [o][m]) via 3-stage cp.async. grid (4, BH).
// ---------------------------------------------------------------------------
__global__ void __launch_bounds__(256)
tc_av2(const __half* __restrict__ xpHT,
       const float* __restrict__ sT, const float* __restrict__ ngT,
       const unsigned* __restrict__ mb,
       const float* __restrict__ bias, float* __restrict__ out)
{
    extern __shared__ char smraw[];
    __shared__ float ngAll[416];
    const int t = threadIdx.x;
    const int n0 = blockIdx.x * 128;
    const int bh = blockIdx.y;
    const int b = bh >> 2, h = bh & 3;

    const int w = t >> 5, lane = t & 31;
    const int g = lane >> 2, tg = lane & 3;
    const int gn0 = n0 + w * 16 + g;
    const int gn1 = gn0 + 8;

    constexpr int STAGE_B = 64 * STU * 4;          // 5120 B
    const uint32_t smb = (uint32_t)__cvta_generic_to_shared(smraw);

    for (int i = t; i < 416; i += 256)
        ngAll[i] = (i < Nn) ? ngT[(size_t)bh * Nn + i] : 0.0f;

    const float sv0 = (gn0 < Nn) ? sT[(size_t)bh * Nn + gn0] : 0.0f;
    const float sv1 = (gn1 < Nn) ? sT[(size_t)bh * Nn + gn1] : 0.0f;

    const __half* Xb = xpHT + (size_t)bh * 64 * Nn;

    float acc[8][4];
    #pragma unroll
    for (int j = 0; j < 8; j++)
        #pragma unroll
        for (int q = 0; q < 4; q++) acc[j][q] = 0.0f;
    float rs0 = 0.0f, rs1 = 0.0f;

    auto stage = [&](int s, int p) {
        const int k0 = s * 32;
        const uint32_t Bs = smb + p * STAGE_B;
        int row = t >> 2, q = t & 3;       // 64 rows x 4 chunks
        int k = k0 + q * 8;
        int sz = (k + 8 <= Nn) ? 16 : 0;
        const void* src = sz ? (const void*)(Xb + (size_t)row * Nn + k) : (const void*)Xb;
        cp16(Bs + (row * STU + q * 4) * 4, src, sz);
        CP_COMMIT();
    };

    stage(0, 0);
    stage(1, 1);
    __syncthreads();   // ngAll visible

    constexpr int S = 13;
    for (int s = 0; s < S; s++) {
        const int p = s % 3;
        if (s + 2 < S) { stage(s + 2, (s + 2) % 3); CP_WAIT(2); }
        else if (s + 1 < S) { CP_WAIT(1); }
        else { CP_WAIT(0); }
        __syncthreads();

        const unsigned w0 = (gn0 < Nn) ? mb[gn0 * 13 + s] : 0xFFFFFFFFu;
        const unsigned w1 = (gn1 < Nn) ? mb[gn1 * 13 + s] : 0xFFFFFFFFu;
        const int m0 = s * 32;
        const uint32_t* Bs = (const uint32_t*)(smraw + p * STAGE_B);

        #pragma unroll
        for (int ks = 0; ks < 2; ks++) {
            const int kb = ks * 8;
            const int ml = ks * 16 + tg * 2;       // local m of a0 halves
            float ngv0 = ngAll[m0 + ml];
            float ngv1 = ngAll[m0 + ml + 1];
            float ngv2 = ngAll[m0 + ml + 8];
            float ngv3 = ngAll[m0 + ml + 9];

            auto ev = [&](float sv, unsigned wm, int mloc, float ng) -> float {
                if ((wm >> mloc) & 1u) return 0.0f;
                float l0 = sv + ng;
                float l = (l0 > 0.0f) ? l0 : LEAKY_C * l0;
                return __expf(l);
            };
            float e00 = ev(sv0, w0, ml, ngv0),     e01 = ev(sv0, w0, ml + 1, ngv1);
            float e02 = ev(sv0, w0, ml + 8, ngv2), e03 = ev(sv0, w0, ml + 9, ngv3);
            float e10 = ev(sv1, w1, ml, ngv0),     e11 = ev(sv1, w1, ml + 1, ngv1);
            float e12 = ev(sv1, w1, ml + 8, ngv2), e13 = ev(sv1, w1, ml + 9, ngv3);
            rs0 += e00 + e01 + e02 + e03;
            rs1 += e10 + e11 + e12 + e13;

            uint32_t af[4];
            __half2 h0 = __floats2half2_rn(e00, e01);
            __half2 h1 = __floats2half2_rn(e10, e11);
            __half2 h2 = __floats2half2_rn(e02, e03);
            __half2 h3 = __floats2half2_rn(e12, e13);
            af[0] = *(uint32_t*)&h0; af[1] = *(uint32_t*)&h1;
            af[2] = *(uint32_t*)&h2; af[3] = *(uint32_t*)&h3;

            #pragma unroll
            for (int nt = 0; nt < 8; nt++) {
                const int c = nt * 8 + g;
                uint32_t b0 = Bs[c * STU + kb + tg];
                uint32_t b1 = Bs[c * STU + kb + tg + 4];
                mma_f16(acc[nt], af, b0, b1);
            }
        }
        __syncthreads();
    }

    // full row sums: reduce over the 4 tg-lanes sharing a row group
    rs0 += __shfl_xor_sync(0xffffffffu, rs0, 1);
    rs0 += __shfl_xor_sync(0xffffffffu, rs0, 2);
    rs1 += __shfl_xor_sync(0xffffffffu, rs1, 1);
    rs1 += __shfl_xor_sync(0xffffffffu, rs1, 2);
    const float inv0 = 1.0f / rs0;
    const float inv1 = 1.0f / rs1;

    #pragma unroll
    for (int nt = 0; nt < 8; nt++) {
        int cc = nt * 8 + tg * 2;
        float2 bb = *(const float2*)(bias + h * 64 + cc);
        if (gn0 < Nn) {
            float v0 = acc[nt][0] * inv0 + bb.x;
            float v1 = acc[nt][1] * inv0 + bb.y;
            v0 = (v0 > 0.0f) ? v0 : expm1f(v0);
            v1 = (v1 > 0.0f) ? v1 : expm1f(v1);
            *(float2*)(out + ((size_t)(b * Nn + gn0)) * 256 + h * 64 + cc) =
                make_float2(v0, v1);
        }
        if (gn1 < Nn) {
            float v0 = acc[nt][2] * inv1 + bb.x;
            float v1 = acc[nt][3] * inv1 + bb.y;
            v0 = (v0 > 0.0f) ? v0 : expm1f(v0);
            v1 = (v1 > 0.0f) ? v1 : expm1f(v1);
            *(float2*)(out + ((size_t)(b * Nn + gn1)) * 256 + h * 64 + cc) =
                make_float2(v0, v1);
        }
    }
}
constexpr unsigned SMEM_AV = 3u * 64u * STU * 4u;   // 15360 B

// ---------------------------------------------------------------------------
// Elementwise fp32 -> fp16
// ---------------------------------------------------------------------------
__global__ void k_f2h(const float* __restrict__ in, __half* __restrict__ out,
                      size_t n4)
{
    size_t i = (size_t)blockIdx.x * blockDim.x + threadIdx.x;
    if (i >= n4) return;
    float4 v = *(const float4*)(in + i * 4);
    *(__half2*)(out + i * 4) = __floats2half2_rn(v.x, v.y);
    *(__half2*)(out + i * 4 + 2) = __floats2half2_rn(v.z, v.w);
}

// ---------------------------------------------------------------------------
// Transpose fp32 -> fp16
// ---------------------------------------------------------------------------
__global__ void k_transpose_h(const float* __restrict__ in, __half* __restrict__ out,
                              int R, int C, long sIn, long sOut)
{
    __shared__ float tile[32][33];
    in += (size_t)blockIdx.z * sIn;
    out += (size_t)blockIdx.z * sOut;
    int c = blockIdx.x * 32 + threadIdx.x;
    int r = blockIdx.y * 32 + threadIdx.y;
    #pragma unroll
    for (int i = 0; i < 4; i++) {
        int rr = r + i * 8;
        if (rr < R && c < C) tile[threadIdx.y + i * 8][threadIdx.x] = in[(size_t)rr * C + c];
    }
    __syncthreads();
    int c2 = blockIdx.y * 32 + threadIdx.x;
    int r2 = blockIdx.x * 32 + threadIdx.y;
    #pragma unroll
    for (int i = 0; i < 4; i++) {
        int rr = r2 + i * 8;
        if (rr < C && c2 < R)
            out[(size_t)rr * R + c2] = __float2half_rn(tile[threadIdx.x][threadIdx.y + i * 8]);
    }
}

// ---------------------------------------------------------------------------
// Transpose fp16 -> fp16 (via fp32 tile)
// ---------------------------------------------------------------------------
__global__ void k_transpose_hh(const __half* __restrict__ in, __half* __restrict__ out,
                               int R, int C, long sIn, long sOut)
{
    __shared__ float tile[32][33];
    in += (size_t)blockIdx.z * sIn;
    out += (size_t)blockIdx.z * sOut;
    int c = blockIdx.x * 32 + threadIdx.x;
    int r = blockIdx.y * 32 + threadIdx.y;
    #pragma unroll
    for (int i = 0; i < 4; i++) {
        int rr = r + i * 8;
        if (rr < R && c < C)
            tile[threadIdx.y + i * 8][threadIdx.x] = __half2float(in[(size_t)rr * C + c]);
    }
    __syncthreads();
    int c2 = blockIdx.y * 32 + threadIdx.x;
    int r2 = blockIdx.x * 32 + threadIdx.y;
    #pragma unroll
    for (int i = 0; i < 4; i++) {
        int rr = r2 + i * 8;
        if (rr < C && c2 < R)
            out[(size_t)rr * R + c2] = __float2half_rn(tile[threadIdx.x][threadIdx.y + i * 8]);
    }
}

// ---------------------------------------------------------------------------
// xpH [b,n,256] fp16 -> xpHT [(b,h), o, m] fp16
// ---------------------------------------------------------------------------
__global__ void k_xpT(const __half* __restrict__ xp, __half* __restrict__ xpHT)
{
    __shared__ float tile[32][33];
    const int bh = blockIdx.z;
    const int b = bh >> 2, h = bh & 3;
    int o = blockIdx.y * 32 + threadIdx.x;
    int n = blockIdx.x * 32 + threadIdx.y;
    #pragma unroll
    for (int i = 0; i < 4; i++) {
        int nn = n + i * 8;
        if (nn < Nn)
            tile[threadIdx.y + i * 8][threadIdx.x] =
                __half2float(xp[((size_t)(b * Nn + nn)) * 256 + h * 64 + o]);
    }
    __syncthreads();
    int n2 = blockIdx.x * 32 + threadIdx.x;
    int o2 = blockIdx.y * 32 + threadIdx.y;
    #pragma unroll
    for (int i = 0; i < 4; i++) {
        int oo = o2 + i * 8;
        if (n2 < Nn)
            xpHT[((size_t)bh * 64 + oo) * Nn + n2] =
                __float2half_rn(tile[threadIdx.x][threadIdx.y + i * 8]);
    }
}

// ---------------------------------------------------------------------------
// Mask bitmap (bits set for masked-out OR out-of-range m)
// ---------------------------------------------------------------------------
__global__ void k_mask(const float* __restrict__ a, unsigned* __restrict__ mb)
{
    int i = blockIdx.x * blockDim.x + threadIdx.x;
    if (i >= Nn * 13) return;
    int n = i / 13, w = i - n * 13;
    unsigned bits = 0;
    #pragma unroll
    for (int j = 0; j < 32; j++) {
        int m = w * 32 + j;
        bool masked = (m >= Nn) || (m != n && a[(size_t)n * Nn + m] == 0.0f);
        if (masked) bits |= 1u << j;
    }
    mb[i] = bits;
}

// ---------------------------------------------------------------------------
// kak[i][h*2+0] = sum_o kern[i,h,o]*ak_self[o,h]; +1 for neigh
// 1024 threads: (i,h) pairs
// ---------------------------------------------------------------------------
__global__ void k_kak(const float* __restrict__ kern,
                      const float* __restrict__ aks,
                      const float* __restrict__ akn,
                      float* __restrict__ kak)
{
    int idx = blockIdx.x * blockDim.x + threadIdx.x;
    if (idx >= 256 * 4) return;
    int i = idx >> 2, h = idx & 3;
    float s = 0.0f, n = 0.0f;
    #pragma unroll 8
    for (int o = 0; o < 64; o++) {
        float kv = kern[i * 256 + h * 64 + o];
        s += kv * aks[o * 4 + h];
        n += kv * akn[o * 4 + h];
    }
    kak[i * 8 + h * 2 + 0] = s;
    kak[i * 8 + h * 2 + 1] = n;
}

// ---------------------------------------------------------------------------
// s/ng from zH: warp per (b,n); 8 outputs = 4 heads x {self, neigh}
// ---------------------------------------------------------------------------
__global__ void k_proj2(const __half* __restrict__ zH,
                        const float* __restrict__ kak,
                        float* __restrict__ sT, float* __restrict__ ngT)
{
    int gw = (blockIdx.x * blockDim.x + threadIdx.x) >> 5;
    int lane = threadIdx.x & 31;
    if (gw >= BN) return;
    int b = gw / Nn, n = gw - b * Nn;
    const __half* zr = zH + (size_t)gw * HO + lane * 8;
    float zf[8];
    #pragma unroll
    for (int j = 0; j < 4; j++) {
        float2 v = __half22float2(*(const __half2*)(zr + j * 2));
        zf[j * 2] = v.x; zf[j * 2 + 1] = v.y;
    }
    const float* kr = kak + (lane * 8) * 8;
    float o[8] = {};
    #pragma unroll
    for (int j = 0; j < 8; j++) {
        float4 k0 = *(const float4*)(kr + j * 8);
        float4 k1 = *(const float4*)(kr + j * 8 + 4);
        o[0] += zf[j] * k0.x; o[1] += zf[j] * k0.y;
        o[2] += zf[j] * k0.z; o[3] += zf[j] * k0.w;
        o[4] += zf[j] * k1.x; o[5] += zf[j] * k1.y;
        o[6] += zf[j] * k1.z; o[7] += zf[j] * k1.w;
    }
    #pragma unroll
    for (int q = 0; q < 8; q++) {
        #pragma unroll
        for (int off = 16; off > 0; off >>= 1)
            o[q] += __shfl_down_sync(0xffffffffu, o[q], off);
    }
    if (lane == 0) {
        #pragma unroll
        for (int h = 0; h < 4; h++) {
            sT[((size_t)(b * Hh + h)) * Nn + n] = o[h * 2 + 0];
            ngT[((size_t)(b * Hh + h)) * Nn + n] = o[h * 2 + 1];
        }
    }
}

// ---------------------------------------------------------------------------
extern "C" void kernel_launch(void* const* d_in, const int* in_sizes, int n_in,
                              void* d_out, int out_size)
{
    const float* x        = (const float*)d_in[0];
    const float* a        = (const float*)d_in[1];
    const float* w_mlp    = (const float*)d_in[2];
    const float* b_mlp    = (const float*)d_in[3];
    const float* kern     = (const float*)d_in[4];
    const float* ak_self  = (const float*)d_in[5];
    const float* ak_neigh = (const float*)d_in[6];
    const float* bias     = (const float*)d_in[7];
    float* out = (float*)d_out;

    __half *p_xH, *p_wTh, *p_kTh, *p_aH, *p_mlpH, *p_mlpTh, *p_zH, *p_xpH, *p_xpHT;
    float *p_kak, *p_sT, *p_ngT;
    unsigned* p_mbits;
    cudaGetSymbolAddress((void**)&p_xH, g_xH);
    cudaGetSymbolAddress((void**)&p_wTh, g_wTh);
    cudaGetSymbolAddress((void**)&p_kTh, g_kTh);
    cudaGetSymbolAddress((void**)&p_aH, g_aH);
    cudaGetSymbolAddress((void**)&p_mlpH, g_mlpH);
    cudaGetSymbolAddress((void**)&p_mlpTh, g_mlpTh);
    cudaGetSymbolAddress((void**)&p_zH, g_zH);
    cudaGetSymbolAddress((void**)&p_xpH, g_xpH);
    cudaGetSymbolAddress((void**)&p_xpHT, g_xpHT);
    cudaGetSymbolAddress((void**)&p_kak, g_kak);
    cudaGetSymbolAddress((void**)&p_sT, g_sT);
    cudaGetSymbolAddress((void**)&p_ngT, g_ngT);
    cudaGetSymbolAddress((void**)&p_mbits, g_mbits);

    cudaFuncSetAttribute(tc_gemm<0>, cudaFuncAttributeMaxDynamicSharedMemorySize, SMEM_TC);
    cudaFuncSetAttribute(tc_gemm<1>, cudaFuncAttributeMaxDynamicSharedMemorySize, SMEM_TC);
    cudaFuncSetAttribute(tc_gemm<2>, cudaFuncAttributeMaxDynamicSharedMemorySize, SMEM_TC);

    // prep
    k_f2h<<<((size_t)BN * HO / 4 + 255) / 256, 256>>>(x, p_xH, (size_t)BN * HO / 4);
    k_f2h<<<(Nn * Nn / 4 + 255) / 256, 256>>>(a, p_aH, Nn * Nn / 4);
    k_transpose_h<<<dim3(8, 8, 1), dim3(32, 8)>>>(w_mlp, p_wTh, 256, 256, 0, 0);
    k_transpose_h<<<dim3(8, 8, 1), dim3(32, 8)>>>(kern, p_kTh, 256, 256, 0, 0);
    k_mask<<<(Nn * 13 + 127) / 128, 128>>>(a, p_mbits);
    k_kak<<<4, 256>>>(kern, ak_self, ak_neigh, p_kak);

    // 1. mlp = sigmoid(x @ w_mlp + b)  -> fp16
    tc_gemm<0><<<dim3((BN + 127) / 128, 2, 1), 256, SMEM_TC>>>(
        p_xH, 0, p_wTh, 0, b_mlp, 0, p_mlpH, 0, BN, 256, 8);
    // 2. mlpT per batch
    k_transpose_hh<<<dim3(8, 13, Bb), dim3(32, 8)>>>(p_mlpH, p_mlpTh, Nn, 256,
                                                     (long)Nn * 256, (long)Nn * 256);
    // 3. z = 0.8*a@mlp + 0.2*mlp       -> fp16
    tc_gemm<2><<<dim3(4, 2, Bb), 256, SMEM_TC>>>(
        p_aH, 0, p_mlpTh, (long)Nn * 256, p_mlpH, (long)Nn * 256,
        p_zH, (long)Nn * 256, Nn, Nn, 13);
    // 4. xp = z @ kernel               -> fp16
    tc_gemm<1><<<dim3((BN + 127) / 128, 2, 1), 256, SMEM_TC>>>(
        p_zH, 0, p_kTh, 0, nullptr, 0, p_xpH, 0, BN, 256, 8);
    // 5. s/ng from z via collapsed attention vectors
    k_proj2<<<(BN * 32 + 255) / 256, 256>>>(p_zH, p_kak, p_sT, p_ngT);
    // 6. xp -> transposed per (b,h)
    k_xpT<<<dim3(13, 2, BH), dim3(32, 8)>>>(p_xpH, p_xpHT);
    // 7. fused attention: inline E + AV + softmax-normalize + bias + ELU
    tc_av2<<<dim3(4, BH), 256, SMEM_AV>>>(p_xpHT, p_sT, p_ngT, p_mbits, bias, out);
}